// round 1
// baseline (speedup 1.0000x reference)
#include <cuda_runtime.h>
#include <cstdint>
#include <cstddef>

// Problem constants: B=1, N=2048, C=1024, H=8, D=128
#define NTOK 2048
#define HEADS 8
#define DHEAD 128

// ---------------- scratch (static device globals; no runtime alloc) ----------------
__device__ float g_qkv_cls[(size_t)NTOK * 3072];            // [n][s*1024 + h*128 + d]
__device__ float g_qk_reg [(size_t)NTOK * 2048];            // [n][s*1024 + h*128 + d], s in {q,k}
__device__ float g_vnorm  [(size_t)HEADS * NTOK * DHEAD];   // [h][n][d] l2-normalized v
__device__ float g_Scls   [(size_t)HEADS * NTOK * NTOK];    // q_cls.k_cls^T, overwritten by P
__device__ float g_Sreg   [(size_t)HEADS * NTOK * NTOK];    // q_reg.k_reg^T
__device__ float g_Svv    [(size_t)HEADS * NTOK * NTOK];    // vnorm.vnorm^T

// ---------------- generic 128x128x16 SGEMM, 256 threads, 8x8 microtile ----------------
// C[n][m] (+head offsets) = sum_k A[n][k] * (TB ? B[m][k] : B[k][m])
template<bool TB>
__global__ __launch_bounds__(256) void sgemm_t(
    const float* __restrict__ A, const float* __restrict__ B, float* __restrict__ C,
    int lda, int ldb, int ldc,
    size_t aH, size_t bH, size_t cH, int K)
{
    __shared__ float As[16][136];
    __shared__ float Bs[16][136];
    A += (size_t)blockIdx.z * aH;
    B += (size_t)blockIdx.z * bH;
    C += (size_t)blockIdx.z * cH;
    const int m0 = blockIdx.x * 128;
    const int n0 = blockIdx.y * 128;
    const int tid = threadIdx.x;
    const int tx = tid & 15, ty = tid >> 4;
    const int arow = tid >> 1;          // 0..127
    const int akg  = (tid & 1) * 8;     // 0 or 8
    const int brow = tid >> 4;          // 0..15  (NN B load)
    const int bcol = (tid & 15) * 8;    // 0..120

    float acc[8][8];
#pragma unroll
    for (int i = 0; i < 8; i++)
#pragma unroll
        for (int j = 0; j < 8; j++) acc[i][j] = 0.0f;

    for (int k0 = 0; k0 < K; k0 += 16) {
        float4 a0 = *(const float4*)(A + (size_t)(n0 + arow) * lda + k0 + akg);
        float4 a1 = *(const float4*)(A + (size_t)(n0 + arow) * lda + k0 + akg + 4);
        float4 b0, b1;
        if (TB) {
            b0 = *(const float4*)(B + (size_t)(m0 + arow) * ldb + k0 + akg);
            b1 = *(const float4*)(B + (size_t)(m0 + arow) * ldb + k0 + akg + 4);
        } else {
            b0 = *(const float4*)(B + (size_t)(k0 + brow) * ldb + m0 + bcol);
            b1 = *(const float4*)(B + (size_t)(k0 + brow) * ldb + m0 + bcol + 4);
        }
        __syncthreads();   // previous tile fully consumed
        As[akg + 0][arow] = a0.x; As[akg + 1][arow] = a0.y;
        As[akg + 2][arow] = a0.z; As[akg + 3][arow] = a0.w;
        As[akg + 4][arow] = a1.x; As[akg + 5][arow] = a1.y;
        As[akg + 6][arow] = a1.z; As[akg + 7][arow] = a1.w;
        if (TB) {
            Bs[akg + 0][arow] = b0.x; Bs[akg + 1][arow] = b0.y;
            Bs[akg + 2][arow] = b0.z; Bs[akg + 3][arow] = b0.w;
            Bs[akg + 4][arow] = b1.x; Bs[akg + 5][arow] = b1.y;
            Bs[akg + 6][arow] = b1.z; Bs[akg + 7][arow] = b1.w;
        } else {
            *(float4*)&Bs[brow][bcol]     = b0;
            *(float4*)&Bs[brow][bcol + 4] = b1;
        }
        __syncthreads();
#pragma unroll
        for (int kk = 0; kk < 16; kk++) {
            float a[8], b[8];
            *(float4*)(a)     = *(const float4*)&As[kk][ty * 8];
            *(float4*)(a + 4) = *(const float4*)&As[kk][ty * 8 + 4];
            *(float4*)(b)     = *(const float4*)&Bs[kk][tx * 8];
            *(float4*)(b + 4) = *(const float4*)&Bs[kk][tx * 8 + 4];
#pragma unroll
            for (int i = 0; i < 8; i++)
#pragma unroll
                for (int j = 0; j < 8; j++)
                    acc[i][j] = fmaf(a[i], b[j], acc[i][j]);
        }
    }
#pragma unroll
    for (int i = 0; i < 8; i++) {
        float* cp = C + (size_t)(n0 + ty * 8 + i) * ldc + m0 + tx * 8;
        *(float4*)(cp)     = make_float4(acc[i][0], acc[i][1], acc[i][2], acc[i][3]);
        *(float4*)(cp + 4) = make_float4(acc[i][4], acc[i][5], acc[i][6], acc[i][7]);
    }
}

// ---------------- L2-normalize the 5 vector families (one warp per 128-vector) ------
__global__ __launch_bounds__(256) void normalize_k()
{
    const int gid  = blockIdx.x * 8 + (threadIdx.x >> 5); // global warp id
    const int lane = threadIdx.x & 31;
    // gid in [0, 5*2048*8)
    const int op  = gid / (NTOK * HEADS);
    const int rem = gid - op * (NTOK * HEADS);
    const int n = rem >> 3;
    const int h = rem & 7;

    const float* src;
    float* dst;
    if (op == 0)      { src = g_qkv_cls + (size_t)n * 3072 + h * 128;         dst = (float*)src; }
    else if (op == 1) { src = g_qkv_cls + (size_t)n * 3072 + 1024 + h * 128;  dst = (float*)src; }
    else if (op == 2) { src = g_qk_reg  + (size_t)n * 2048 + h * 128;         dst = (float*)src; }
    else if (op == 3) { src = g_qk_reg  + (size_t)n * 2048 + 1024 + h * 128;  dst = (float*)src; }
    else              { src = g_qkv_cls + (size_t)n * 3072 + 2048 + h * 128;
                        dst = g_vnorm + ((size_t)h * NTOK + n) * DHEAD; }

    float4 v = *(const float4*)(src + lane * 4);
    float ss = v.x * v.x + v.y * v.y + v.z * v.z + v.w * v.w;
#pragma unroll
    for (int o = 16; o; o >>= 1) ss += __shfl_xor_sync(0xffffffffu, ss, o);
    const float r = 1.0f / sqrtf(ss);
    v.x *= r; v.y *= r; v.z *= r; v.w *= r;
    *(float4*)(dst + lane * 4) = v;
}

// ---------------- FMA-only exp (avoid the 0.5ms MUFU wall: rt_MUFU=8/SMSP) ----------
__device__ __forceinline__ float fast_exp(float x)
{
    float t = x * 1.4426950408889634f;         // log2(e)
    t = fmaxf(t, -120.0f);
    float r = t + 12582912.0f;                 // round-to-nearest via 1.5*2^23
    float f = t - (r - 12582912.0f);           // frac in [-0.5, 0.5]
    int   k = __float_as_int(r) - 0x4B400000;  // round(t)
    float p = 1.5403530393381609e-4f;
    p = fmaf(p, f, 1.3333558146428443e-3f);
    p = fmaf(p, f, 9.618129107628477e-3f);
    p = fmaf(p, f, 5.550410866482158e-2f);
    p = fmaf(p, f, 2.402265069591007e-1f);
    p = fmaf(p, f, 6.931471805599453e-1f);
    p = fmaf(p, f, 1.0f);
    return p * __int_as_float((k + 127) << 23);
}

__device__ __forceinline__ float block_max(float v, float* red)
{
#pragma unroll
    for (int o = 16; o; o >>= 1) v = fmaxf(v, __shfl_xor_sync(0xffffffffu, v, o));
    if ((threadIdx.x & 31) == 0) red[threadIdx.x >> 5] = v;
    __syncthreads();
    float r = red[0];
#pragma unroll
    for (int i = 1; i < 8; i++) r = fmaxf(r, red[i]);
    __syncthreads();
    return r;
}

__device__ __forceinline__ float block_sum(float v, float* red)
{
#pragma unroll
    for (int o = 16; o; o >>= 1) v += __shfl_xor_sync(0xffffffffu, v, o);
    if ((threadIdx.x & 31) == 0) red[threadIdx.x >> 5] = v;
    __syncthreads();
    float r = red[0];
#pragma unroll
    for (int i = 1; i < 8; i++) r += red[i];
    __syncthreads();
    return r;
}

// ---------------- fused: dual masked softmax x 8 heads, P (in place over Scls),
//                  sim_attn mean, vv mean, sim softmax + mask + renorm -> sim_round2
__global__ __launch_bounds__(256) void row_fuse(
    const float* __restrict__ cls_score, const float* __restrict__ fg_score,
    float* __restrict__ out_sim)
{
    const int n = blockIdx.x;
    const int tid = threadIdx.x;
    __shared__ float s_sc[NTOK];
    __shared__ float s_fs[NTOK];
    __shared__ float red[8];

#pragma unroll
    for (int j = 0; j < 8; j++) {
        const int m = tid + j * 256;
        s_sc[m] = cls_score[m];
        s_fs[m] = fg_score[m];
    }
    __syncthreads();
    const float cthr = s_sc[n] - 0.1f;
    const float fthr = s_fs[n] - 0.1f;

    float simacc[8], vvacc[8];
#pragma unroll
    for (int j = 0; j < 8; j++) { simacc[j] = 0.0f; vvacc[j] = 0.0f; }

    for (int h = 0; h < HEADS; h++) {
        const size_t base = ((size_t)h * NTOK + n) * NTOK;
        float l[8], p[8];

        // --- cls softmax (multiplicative mask: masked logit == 0, matches reference)
        float mx = -1e30f;
#pragma unroll
        for (int j = 0; j < 8; j++) {
            const int m = tid + j * 256;
            const float s  = g_Scls[base + m];
            const float sc = s_sc[m];
            const float v  = (sc > cthr) ? s * (25.0f * sc) : 0.0f;
            l[j] = v; mx = fmaxf(mx, v);
        }
        mx = block_max(mx, red);
        float sm = 0.0f;
#pragma unroll
        for (int j = 0; j < 8; j++) { l[j] = fast_exp(l[j] - mx); sm += l[j]; }
        sm = block_sum(sm, red);
        float inv = 0.5f / sm;
#pragma unroll
        for (int j = 0; j < 8; j++) p[j] = l[j] * inv;

        // --- reg softmax
        mx = -1e30f;
#pragma unroll
        for (int j = 0; j < 8; j++) {
            const int m = tid + j * 256;
            const float s  = g_Sreg[base + m];
            const float sc = s_fs[m];
            const float v  = (sc > fthr) ? s * (25.0f * sc) : 0.0f;
            l[j] = v; mx = fmaxf(mx, v);
        }
        mx = block_max(mx, red);
        sm = 0.0f;
#pragma unroll
        for (int j = 0; j < 8; j++) { l[j] = fast_exp(l[j] - mx); sm += l[j]; }
        sm = block_sum(sm, red);
        inv = 0.5f / sm;
#pragma unroll
        for (int j = 0; j < 8; j++) {
            p[j] += l[j] * inv;
            g_Scls[base + tid + j * 256] = p[j];   // P overwrites S_cls in place
            simacc[j] += p[j];
            vvacc[j]  += g_Svv[base + tid + j * 256];
        }
    }

    // --- sim_round2: softmax(mean_h P) masked by (mean_h vv > 0.75), renormalized
    float mx = -1e30f;
#pragma unroll
    for (int j = 0; j < 8; j++) { simacc[j] *= 0.125f; mx = fmaxf(mx, simacc[j]); }
    mx = block_max(mx, red);
    float sm = 0.0f;
#pragma unroll
    for (int j = 0; j < 8; j++) { simacc[j] = fast_exp(simacc[j] - mx); sm += simacc[j]; }
    sm = block_sum(sm, red);
    float msum = 0.0f;
#pragma unroll
    for (int j = 0; j < 8; j++) {
        const float soft = simacc[j] / sm;
        const float keep = (vvacc[j] * 0.125f > 0.75f) ? soft : 0.0f;
        simacc[j] = keep; msum += keep;
    }
    msum = block_sum(msum, red);
    const float rn = 1.0f / msum;
#pragma unroll
    for (int j = 0; j < 8; j++)
        out_sim[(size_t)n * NTOK + tid + j * 256] = simacc[j] * rn;
}

// ---------------- x_ori: v-block columns [2048,3072) map straight to out cols [1024,2048)
__global__ __launch_bounds__(256) void copy_xori(float* __restrict__ out)
{
    const size_t i = (size_t)blockIdx.x * 256 + threadIdx.x;  // over 2048*1024
    const int n = (int)(i >> 10);
    const int c = (int)(i & 1023);
    out[(size_t)n * 2048 + 1024 + c] = g_qkv_cls[(size_t)n * 3072 + 2048 + c];
}

// -------------------------------- launch ---------------------------------------------
extern "C" void kernel_launch(void* const* d_in, const int* in_sizes, int n_in,
                              void* d_out, int out_size)
{
    (void)in_sizes; (void)n_in; (void)out_size;
    const float* x_cls     = (const float*)d_in[0];
    const float* x_reg     = (const float*)d_in[1];
    const float* cls_score = (const float*)d_in[2];
    const float* fg_score  = (const float*)d_in[3];
    const float* W_cls     = (const float*)d_in[4];
    const float* W_reg     = (const float*)d_in[5];
    float* out = (float*)d_out;

    float *qkv_cls, *qk_reg, *vnorm, *Scls, *Sreg, *Svv;
    cudaGetSymbolAddress((void**)&qkv_cls, g_qkv_cls);
    cudaGetSymbolAddress((void**)&qk_reg,  g_qk_reg);
    cudaGetSymbolAddress((void**)&vnorm,   g_vnorm);
    cudaGetSymbolAddress((void**)&Scls,    g_Scls);
    cudaGetSymbolAddress((void**)&Sreg,    g_Sreg);
    cudaGetSymbolAddress((void**)&Svv,     g_Svv);

    const size_t SH = (size_t)NTOK * NTOK;     // per-head score-matrix stride
    const size_t VH = (size_t)NTOK * DHEAD;    // per-head vnorm stride
    dim3 blk(256);

    // 1) qkv projections (reg: only q,k columns — V_reg is never used)
    sgemm_t<false><<<dim3(24, 16, 1), blk>>>(x_cls, W_cls, qkv_cls, 1024, 3072, 3072, 0, 0, 0, 1024);
    sgemm_t<false><<<dim3(16, 16, 1), blk>>>(x_reg, W_reg, qk_reg,  1024, 3072, 2048, 0, 0, 0, 1024);

    // 2) l2 normalize q/k (in place) and v -> g_vnorm
    normalize_k<<<5 * NTOK * HEADS / 8, 256>>>();

    // 3) score GEMMs, batched over heads (NT: C = A_rows . B_rows^T)
    sgemm_t<true><<<dim3(16, 16, 8), blk>>>(qkv_cls, qkv_cls + 1024, Scls, 3072, 3072, 2048, 128, 128, SH, 128);
    sgemm_t<true><<<dim3(16, 16, 8), blk>>>(qk_reg,  qk_reg + 1024,  Sreg, 2048, 2048, 2048, 128, 128, SH, 128);
    sgemm_t<true><<<dim3(16, 16, 8), blk>>>(vnorm,   vnorm,          Svv,  128,  128,  2048, VH,  VH,  SH, 128);

    // 4) fused masked softmax + combine + sim_round2 (writes P over g_Scls)
    row_fuse<<<NTOK, 256>>>(cls_score, fg_score, out + (size_t)NTOK * NTOK);

    // 5) x = P @ v_cls  -> out[:, 0:1024] per head
    sgemm_t<false><<<dim3(1, 16, 8), blk>>>(Scls, qkv_cls + 2048, out, 2048, 3072, 2048, SH, 128, 128, 2048);

    // 6) x_ori copy -> out[:, 1024:2048]
    copy_xori<<<(NTOK * 1024) / 256, 256>>>(out);
}

// round 3
// speedup vs baseline: 2.1931x; 2.1931x over previous
#include <cuda_runtime.h>
#include <cuda_bf16.h>
#include <cstdint>
#include <cstddef>

typedef __nv_bfloat16 bf16;
#define NTOK 2048
#define HEADS 8
#define STAGES 3

// ---------------- scratch (static device globals) ----------------
__device__ float g_qkv_cls[(size_t)NTOK * 3072];
__device__ float g_qk_reg [(size_t)NTOK * 2048];
__device__ bf16  g_Xc[(size_t)NTOK * 2048];
__device__ bf16  g_Xr[(size_t)NTOK * 2048];
__device__ bf16  g_Wc[(size_t)3072 * 2048];
__device__ bf16  g_Wr[(size_t)2048 * 2048];
__device__ bf16  g_qc[(size_t)HEADS * NTOK * 256];
__device__ bf16  g_kc[(size_t)HEADS * NTOK * 256];
__device__ bf16  g_qr[(size_t)HEADS * NTOK * 256];
__device__ bf16  g_kr[(size_t)HEADS * NTOK * 256];
__device__ bf16  g_vn[(size_t)HEADS * NTOK * 256];
__device__ bf16  g_Vt[(size_t)HEADS * 128 * 4096];
__device__ float g_Scls[(size_t)HEADS * NTOK * NTOK];
__device__ float g_Sreg[(size_t)HEADS * NTOK * NTOK];
__device__ float g_Svv [(size_t)HEADS * NTOK * NTOK];
__device__ bf16  g_P[(size_t)HEADS * NTOK * 4096];

// ---------------- helpers ----------------
__device__ __forceinline__ uint32_t s2u(const void* p) {
    uint32_t a;
    asm("{ .reg .u64 t; cvta.to.shared.u64 t, %1; cvt.u32.u64 %0, t; }" : "=r"(a) : "l"(p));
    return a;
}
#define SWZ(x) ((x) ^ (((x) >> 3) & 0x70))

__device__ __forceinline__ void cpasync16(uint32_t s, const void* g) {
    asm volatile("cp.async.cg.shared.global [%0], [%1], 16;" :: "r"(s), "l"(g) : "memory");
}
#define CP_COMMIT() asm volatile("cp.async.commit_group;" ::: "memory")
#define CP_WAIT(n)  asm volatile("cp.async.wait_group %0;" :: "n"(n) : "memory")

__device__ __forceinline__ void ldsm4(uint32_t& r0, uint32_t& r1, uint32_t& r2, uint32_t& r3, uint32_t a) {
    asm volatile("ldmatrix.sync.aligned.m8n8.x4.shared.b16 {%0,%1,%2,%3}, [%4];"
                 : "=r"(r0), "=r"(r1), "=r"(r2), "=r"(r3) : "r"(a));
}
__device__ __forceinline__ void mma16816(float* d, const uint32_t* a, uint32_t b0, uint32_t b1) {
    asm volatile(
        "mma.sync.aligned.m16n8k16.row.col.f32.bf16.bf16.f32 "
        "{%0,%1,%2,%3}, {%4,%5,%6,%7}, {%8,%9}, {%0,%1,%2,%3};"
        : "+f"(d[0]), "+f"(d[1]), "+f"(d[2]), "+f"(d[3])
        : "r"(a[0]), "r"(a[1]), "r"(a[2]), "r"(a[3]), "r"(b0), "r"(b1));
}

// ---------------- HMMA NT GEMM with K-concat split ----------------
// C[i][j] = sum over segs { A[i][off_a+k] * B[j][off_b+k] }, segs = (0,0),(K,0),(0,K)
// A: [Mrows][lda] bf16 (lo copy at +K), B likewise. 128x128 tile, 256 thr, 8 warps.
__global__ __launch_bounds__(256) void hm_gemm(
    const bf16* __restrict__ A, const bf16* __restrict__ B, float* __restrict__ C,
    int lda, int ldb, int ldc, size_t aH, size_t bH, size_t cH, int K)
{
    extern __shared__ char dsm[];
    A += blockIdx.z * aH;  B += blockIdx.z * bH;  C += blockIdx.z * cH;
    const int i0 = blockIdx.y * 128, j0 = blockIdx.x * 128;
    const int tid = threadIdx.x;
    const int nkc = K >> 6;          // 64-bf16 chunks per segment
    const int NC  = 3 * nkc;

    const uint32_t stage0 = (s2u(dsm) + 1023u) & ~1023u;

    const int lane = tid & 31, wid = tid >> 5;
    const int wm = wid & 1, wn = wid >> 1;
    const int lt = lane >> 3, lr = lane & 7;
    const int arow = wm * 64 + (lt & 1) * 8 + lr;   // + mt*16
    const int brow = wn * 32 + (lt & 1) * 8 + lr;   // + np*16
    const int kbsub = (lt >> 1) * 16;
    const uint32_t xm = (uint32_t)(lr << 4);

    float acc[4][4][4];
#pragma unroll
    for (int i = 0; i < 4; i++)
#pragma unroll
        for (int j = 0; j < 4; j++)
#pragma unroll
            for (int q = 0; q < 4; q++) acc[i][j][q] = 0.0f;

    // fill one stage with chunk c
    auto fill = [&](int s, int c) {
        const int seg = c / nkc, kk = (c - seg * nkc) << 6;
        const bf16* Ab = A + ((seg == 1) ? K : 0) + kk;
        const bf16* Bb = B + ((seg == 2) ? K : 0) + kk;
        const uint32_t sA = stage0 + (uint32_t)s * 32768u, sB = sA + 16384u;
#pragma unroll
        for (int i = 0; i < 4; i++) {
            const int id = (i << 8) + tid;            // 0..1023
            const int row = id >> 3, c16 = id & 7;
            const uint32_t so = SWZ((uint32_t)((row << 7) + (c16 << 4)));
            cpasync16(sA + so, Ab + (size_t)(i0 + row) * lda + (c16 << 3));
            cpasync16(sB + so, Bb + (size_t)(j0 + row) * ldb + (c16 << 3));
        }
        CP_COMMIT();
    };

#pragma unroll
    for (int c = 0; c < STAGES; c++) fill(c, c);   // NC >= 3 always here

    for (int c = 0; c < NC; ++c) {
        const int s = c - (c / STAGES) * STAGES;
        CP_WAIT(STAGES - 1);
        __syncthreads();
        const uint32_t sA = stage0 + (uint32_t)s * 32768u, sB = sA + 16384u;
#pragma unroll
        for (int ks = 0; ks < 4; ks++) {
            const uint32_t koff = ((uint32_t)(ks * 32 + kbsub)) ^ xm;
            uint32_t a[4][4], b[2][4];
#pragma unroll
            for (int mt = 0; mt < 4; mt++)
                ldsm4(a[mt][0], a[mt][1], a[mt][2], a[mt][3],
                      sA + (uint32_t)((arow + mt * 16) << 7) + koff);
#pragma unroll
            for (int np = 0; np < 2; np++)
                ldsm4(b[np][0], b[np][1], b[np][2], b[np][3],
                      sB + (uint32_t)((brow + np * 16) << 7) + koff);
#pragma unroll
            for (int mt = 0; mt < 4; mt++)
#pragma unroll
                for (int nt = 0; nt < 4; nt++)
                    mma16816(acc[mt][nt], a[mt], b[nt >> 1][nt & 1], b[nt >> 1][(nt & 1) + 2]);
        }
        __syncthreads();
        if (c + STAGES < NC) fill(s, c + STAGES);
        else CP_COMMIT();                            // keep wait_group accounting exact
    }

    // epilogue: direct float2 stores
    const int rq = lane >> 2, cq = (lane & 3) * 2;
#pragma unroll
    for (int mt = 0; mt < 4; mt++) {
        const int row = i0 + wm * 64 + mt * 16 + rq;
#pragma unroll
        for (int nt = 0; nt < 4; nt++) {
            const int col = j0 + wn * 32 + nt * 8 + cq;
            *(float2*)(C + (size_t)row * ldc + col)       = make_float2(acc[mt][nt][0], acc[mt][nt][1]);
            *(float2*)(C + (size_t)(row + 8) * ldc + col) = make_float2(acc[mt][nt][2], acc[mt][nt][3]);
        }
    }
}

// ---------------- fp32 -> bf16 hi|lo split (no transpose) ----------------
__global__ __launch_bounds__(256) void split_x(const float* __restrict__ xc, const float* __restrict__ xr)
{
    const size_t i = (size_t)blockIdx.x * 256 + threadIdx.x;  // over 2048*1024
    const int n = (int)(i >> 10), c = (int)(i & 1023);
    const float v = (blockIdx.z == 0 ? xc : xr)[i];
    bf16* o = (blockIdx.z == 0 ? g_Xc : g_Xr) + (size_t)n * 2048 + c;
    const bf16 h = __float2bfloat16(v);
    o[0] = h;  o[1024] = __float2bfloat16(v - __bfloat162float(h));
}

// ---------------- transpose + split: in fp32 [R][C] -> out bf16 [C][ldout], lo at +R ------
__global__ __launch_bounds__(256) void transpose_split(
    const float* __restrict__ in, bf16* __restrict__ out,
    int R, int C, int ldin, int ldout, size_t zin, size_t zout)
{
    __shared__ float t[32][33];
    in  += (size_t)blockIdx.z * zin;
    out += (size_t)blockIdx.z * zout;
    const int r0 = blockIdx.y * 32, c0 = blockIdx.x * 32;
    const int tx = threadIdx.x & 31, ty = threadIdx.x >> 5;
#pragma unroll
    for (int i = 0; i < 4; i++)
        t[ty + i * 8][tx] = in[(size_t)(r0 + ty + i * 8) * ldin + c0 + tx];
    __syncthreads();
#pragma unroll
    for (int i = 0; i < 4; i++) {
        const int cc = ty + i * 8;
        const float v = t[tx][cc];
        const bf16 h = __float2bfloat16(v);
        out[(size_t)(c0 + cc) * ldout + r0 + tx]     = h;
        out[(size_t)(c0 + cc) * ldout + R + r0 + tx] = __float2bfloat16(v - __bfloat162float(h));
    }
}

// ---------------- L2-normalize + split into per-head K-major bf16 hi|lo ----------------
__global__ __launch_bounds__(256) void normalize_k()
{
    const int gid  = blockIdx.x * 8 + (threadIdx.x >> 5);
    const int lane = threadIdx.x & 31;
    const int op  = gid / (NTOK * HEADS);
    const int rem = gid - op * (NTOK * HEADS);
    const int n = rem >> 3, h = rem & 7;

    const float* src; bf16* dst;
    if (op == 0)      { src = g_qkv_cls + (size_t)n * 3072 + h * 128;        dst = g_qc; }
    else if (op == 1) { src = g_qkv_cls + (size_t)n * 3072 + 1024 + h * 128; dst = g_kc; }
    else if (op == 2) { src = g_qk_reg  + (size_t)n * 2048 + h * 128;        dst = g_qr; }
    else if (op == 3) { src = g_qk_reg  + (size_t)n * 2048 + 1024 + h * 128; dst = g_kr; }
    else              { src = g_qkv_cls + (size_t)n * 3072 + 2048 + h * 128; dst = g_vn; }
    dst += ((size_t)h * NTOK + n) * 256;

    float4 v = *(const float4*)(src + lane * 4);
    float ss = v.x * v.x + v.y * v.y + v.z * v.z + v.w * v.w;
#pragma unroll
    for (int o = 16; o; o >>= 1) ss += __shfl_xor_sync(0xffffffffu, ss, o);
    const float r = 1.0f / sqrtf(ss);
    float a[4] = { v.x * r, v.y * r, v.z * r, v.w * r };
#pragma unroll
    for (int j = 0; j < 4; j++) {
        const bf16 h2 = __float2bfloat16(a[j]);
        dst[lane * 4 + j]       = h2;
        dst[128 + lane * 4 + j] = __float2bfloat16(a[j] - __bfloat162float(h2));
    }
}

// ---------------- FMA-only exp + block reductions ----------------
__device__ __forceinline__ float fast_exp(float x)
{
    float t = x * 1.4426950408889634f;
    t = fmaxf(t, -120.0f);
    float r = t + 12582912.0f;
    float f = t - (r - 12582912.0f);
    int   k = __float_as_int(r) - 0x4B400000;
    float p = 1.5403530393381609e-4f;
    p = fmaf(p, f, 1.3333558146428443e-3f);
    p = fmaf(p, f, 9.618129107628477e-3f);
    p = fmaf(p, f, 5.550410866482158e-2f);
    p = fmaf(p, f, 2.402265069591007e-1f);
    p = fmaf(p, f, 6.931471805599453e-1f);
    p = fmaf(p, f, 1.0f);
    return p * __int_as_float((k + 127) << 23);
}
__device__ __forceinline__ float block_max(float v, float* red)
{
#pragma unroll
    for (int o = 16; o; o >>= 1) v = fmaxf(v, __shfl_xor_sync(0xffffffffu, v, o));
    if ((threadIdx.x & 31) == 0) red[threadIdx.x >> 5] = v;
    __syncthreads();
    float r = red[0];
#pragma unroll
    for (int i = 1; i < 8; i++) r = fmaxf(r, red[i]);
    __syncthreads();
    return r;
}
__device__ __forceinline__ float block_sum(float v, float* red)
{
#pragma unroll
    for (int o = 16; o; o >>= 1) v += __shfl_xor_sync(0xffffffffu, v, o);
    if ((threadIdx.x & 31) == 0) red[threadIdx.x >> 5] = v;
    __syncthreads();
    float r = red[0];
#pragma unroll
    for (int i = 1; i < 8; i++) r += red[i];
    __syncthreads();
    return r;
}

// ---------------- fused masked dual softmax + combine + sim_round2; P out bf16 hi|lo ----
__global__ __launch_bounds__(256) void row_fuse(
    const float* __restrict__ cls_score, const float* __restrict__ fg_score,
    float* __restrict__ out_sim)
{
    const int n = blockIdx.x;
    const int tid = threadIdx.x;
    __shared__ float s_sc[NTOK];
    __shared__ float s_fs[NTOK];
    __shared__ float red[8];

#pragma unroll
    for (int j = 0; j < 8; j++) {
        const int m = tid + j * 256;
        s_sc[m] = cls_score[m];
        s_fs[m] = fg_score[m];
    }
    __syncthreads();
    const float cthr = s_sc[n] - 0.1f;
    const float fthr = s_fs[n] - 0.1f;

    float simacc[8], vvacc[8];
#pragma unroll
    for (int j = 0; j < 8; j++) { simacc[j] = 0.0f; vvacc[j] = 0.0f; }

    for (int h = 0; h < HEADS; h++) {
        const size_t base = ((size_t)h * NTOK + n) * NTOK;
        bf16* Pb = g_P + ((size_t)h * NTOK + n) * 4096;
        float l[8], p[8];

        float mx = -1e30f;
#pragma unroll
        for (int j = 0; j < 8; j++) {
            const int m = tid + j * 256;
            const float s  = g_Scls[base + m];
            const float sc = s_sc[m];
            const float v  = (sc > cthr) ? s * (25.0f * sc) : 0.0f;
            l[j] = v; mx = fmaxf(mx, v);
        }
        mx = block_max(mx, red);
        float sm = 0.0f;
#pragma unroll
        for (int j = 0; j < 8; j++) { l[j] = fast_exp(l[j] - mx); sm += l[j]; }
        sm = block_sum(sm, red);
        float inv = 0.5f / sm;
#pragma unroll
        for (int j = 0; j < 8; j++) p[j] = l[j] * inv;

        mx = -1e30f;
#pragma unroll
        for (int j = 0; j < 8; j++) {
            const int m = tid + j * 256;
            const float s  = g_Sreg[base + m];
            const float sc = s_fs[m];
            const float v  = (sc > fthr) ? s * (25.0f * sc) : 0.0f;
            l[j] = v; mx = fmaxf(mx, v);
        }
        mx = block_max(mx, red);
        sm = 0.0f;
#pragma unroll
        for (int j = 0; j < 8; j++) { l[j] = fast_exp(l[j] - mx); sm += l[j]; }
        sm = block_sum(sm, red);
        inv = 0.5f / sm;
#pragma unroll
        for (int j = 0; j < 8; j++) {
            const int m = tid + j * 256;
            const float pv = p[j] + l[j] * inv;
            const bf16 hh = __float2bfloat16(pv);
            Pb[m]        = hh;
            Pb[2048 + m] = __float2bfloat16(pv - __bfloat162float(hh));
            simacc[j] += pv;
            vvacc[j]  += g_Svv[base + m];
        }
    }

    float mx = -1e30f;
#pragma unroll
    for (int j = 0; j < 8; j++) { simacc[j] *= 0.125f; mx = fmaxf(mx, simacc[j]); }
    mx = block_max(mx, red);
    float sm = 0.0f;
#pragma unroll
    for (int j = 0; j < 8; j++) { simacc[j] = fast_exp(simacc[j] - mx); sm += simacc[j]; }
    sm = block_sum(sm, red);
    float msum = 0.0f;
#pragma unroll
    for (int j = 0; j < 8; j++) {
        const float soft = simacc[j] / sm;
        const float keep = (vvacc[j] * 0.125f > 0.75f) ? soft : 0.0f;
        simacc[j] = keep; msum += keep;
    }
    msum = block_sum(msum, red);
    const float rn = 1.0f / msum;
#pragma unroll
    for (int j = 0; j < 8; j++)
        out_sim[(size_t)n * NTOK + tid + j * 256] = simacc[j] * rn;
}

// ---------------- x_ori copy ----------------
__global__ __launch_bounds__(256) void copy_xori(float* __restrict__ out)
{
    const size_t i = (size_t)blockIdx.x * 256 + threadIdx.x;
    const int n = (int)(i >> 10);
    const int c = (int)(i & 1023);
    out[(size_t)n * 2048 + 1024 + c] = g_qkv_cls[(size_t)n * 3072 + 2048 + c];
}

// -------------------------------- launch ----------------------------------------
extern "C" void kernel_launch(void* const* d_in, const int* in_sizes, int n_in,
                              void* d_out, int out_size)
{
    (void)in_sizes; (void)n_in; (void)out_size;
    const float* x_cls     = (const float*)d_in[0];
    const float* x_reg     = (const float*)d_in[1];
    const float* cls_score = (const float*)d_in[2];
    const float* fg_score  = (const float*)d_in[3];
    const float* W_cls     = (const float*)d_in[4];
    const float* W_reg     = (const float*)d_in[5];
    float* out = (float*)d_out;

    float *qkv_cls, *qk_reg, *Scls, *Sreg, *Svv;
    bf16 *Xc, *Xr, *Wc, *Wr, *qc, *kc, *qr, *kr, *vn, *Vt, *P;
    cudaGetSymbolAddress((void**)&qkv_cls, g_qkv_cls);
    cudaGetSymbolAddress((void**)&qk_reg,  g_qk_reg);
    cudaGetSymbolAddress((void**)&Xc, g_Xc);  cudaGetSymbolAddress((void**)&Xr, g_Xr);
    cudaGetSymbolAddress((void**)&Wc, g_Wc);  cudaGetSymbolAddress((void**)&Wr, g_Wr);
    cudaGetSymbolAddress((void**)&qc, g_qc);  cudaGetSymbolAddress((void**)&kc, g_kc);
    cudaGetSymbolAddress((void**)&qr, g_qr);  cudaGetSymbolAddress((void**)&kr, g_kr);
    cudaGetSymbolAddress((void**)&vn, g_vn);  cudaGetSymbolAddress((void**)&Vt, g_Vt);
    cudaGetSymbolAddress((void**)&Scls, g_Scls);
    cudaGetSymbolAddress((void**)&Sreg, g_Sreg);
    cudaGetSymbolAddress((void**)&Svv,  g_Svv);
    cudaGetSymbolAddress((void**)&P,    g_P);

    const int DS = STAGES * 32768 + 1024;
    cudaFuncSetAttribute(hm_gemm, cudaFuncAttributeMaxDynamicSharedMemorySize, DS);

    const size_t SH = (size_t)NTOK * NTOK;
    const size_t QH = (size_t)NTOK * 256;

    // 1) split inputs, transpose+split weights
    split_x<<<dim3(8192, 1, 2), 256>>>(x_cls, x_reg);
    transpose_split<<<dim3(96, 32, 1), 256>>>(W_cls, Wc, 1024, 3072, 3072, 2048, 0, 0);
    transpose_split<<<dim3(64, 32, 1), 256>>>(W_reg, Wr, 1024, 2048, 3072, 2048, 0, 0);

    // 2) qkv projections (HMMA, split fp32 emulation)
    hm_gemm<<<dim3(24, 16, 1), 256, DS>>>(Xc, Wc, qkv_cls, 2048, 2048, 3072, 0, 0, 0, 1024);
    hm_gemm<<<dim3(16, 16, 1), 256, DS>>>(Xr, Wr, qk_reg,  2048, 2048, 2048, 0, 0, 0, 1024);

    // 3) normalize q/k/v -> per-head split bf16; transpose v -> Vt split
    normalize_k<<<5 * NTOK * HEADS / 8, 256>>>();
    transpose_split<<<dim3(4, 64, 8), 256>>>(qkv_cls + 2048, Vt, 2048, 128, 3072, 4096,
                                             128, (size_t)128 * 4096);

    // 4) score GEMMs (batched over heads)
    hm_gemm<<<dim3(16, 16, 8), 256, DS>>>(qc, kc, Scls, 256, 256, 2048, QH, QH, SH, 128);
    hm_gemm<<<dim3(16, 16, 8), 256, DS>>>(qr, kr, Sreg, 256, 256, 2048, QH, QH, SH, 128);
    hm_gemm<<<dim3(16, 16, 8), 256, DS>>>(vn, vn, Svv,  256, 256, 2048, QH, QH, SH, 128);

    // 5) fused softmax etc; writes P (bf16 hi|lo) + sim output
    row_fuse<<<NTOK, 256>>>(cls_score, fg_score, out + (size_t)NTOK * NTOK);

    // 6) x = P @ V  -> out[:, 0:1024] per head
    hm_gemm<<<dim3(1, 16, 8), 256, DS>>>(P, Vt, out, 4096, 4096, 2048,
                                         (size_t)NTOK * 4096, (size_t)128 * 4096, 128, 2048);

    // 7) x_ori copy -> out[:, 1024:2048]
    copy_xori<<<(NTOK * 1024) / 256, 256>>>(out);
}

// round 4
// speedup vs baseline: 2.2139x; 1.0095x over previous
#include <cuda_runtime.h>
#include <cuda_bf16.h>
#include <cstdint>
#include <cstddef>

typedef __nv_bfloat16 bf16;
#define NTOK 2048
#define HEADS 8
#define STAGES 3

// ---------------- scratch (static device globals) ----------------
__device__ float g_qkv_cls[(size_t)NTOK * 3072];
__device__ float g_qk_reg [(size_t)NTOK * 2048];
__device__ bf16  g_Xc[(size_t)NTOK * 2048];
__device__ bf16  g_Xr[(size_t)NTOK * 2048];
__device__ bf16  g_Wc[(size_t)3072 * 2048];
__device__ bf16  g_Wr[(size_t)2048 * 2048];
__device__ bf16  g_qc[(size_t)HEADS * NTOK * 256];
__device__ bf16  g_kc[(size_t)HEADS * NTOK * 256];
__device__ bf16  g_qr[(size_t)HEADS * NTOK * 256];
__device__ bf16  g_kr[(size_t)HEADS * NTOK * 256];
__device__ bf16  g_vn[(size_t)HEADS * NTOK * 256];
__device__ bf16  g_Vt[(size_t)HEADS * 128 * 4096];
__device__ float g_Scls[(size_t)HEADS * NTOK * NTOK];
__device__ float g_Sreg[(size_t)HEADS * NTOK * NTOK];
__device__ float g_Svv [(size_t)HEADS * NTOK * NTOK];
__device__ bf16  g_P[(size_t)HEADS * NTOK * 4096];

// ---------------- helpers ----------------
__device__ __forceinline__ uint32_t s2u(const void* p) {
    uint32_t a;
    asm("{ .reg .u64 t; cvta.to.shared.u64 t, %1; cvt.u32.u64 %0, t; }" : "=r"(a) : "l"(p));
    return a;
}
#define SWZ(x) ((x) ^ (((x) >> 3) & 0x70))

__device__ __forceinline__ void cpasync16(uint32_t s, const void* g) {
    asm volatile("cp.async.cg.shared.global [%0], [%1], 16;" :: "r"(s), "l"(g) : "memory");
}
#define CP_COMMIT() asm volatile("cp.async.commit_group;" ::: "memory")
#define CP_WAIT(n)  asm volatile("cp.async.wait_group %0;" :: "n"(n) : "memory")

__device__ __forceinline__ void ldsm4(uint32_t& r0, uint32_t& r1, uint32_t& r2, uint32_t& r3, uint32_t a) {
    asm volatile("ldmatrix.sync.aligned.m8n8.x4.shared.b16 {%0,%1,%2,%3}, [%4];"
                 : "=r"(r0), "=r"(r1), "=r"(r2), "=r"(r3) : "r"(a));
}
__device__ __forceinline__ void mma16816(float* d, const uint32_t* a, uint32_t b0, uint32_t b1) {
    asm volatile(
        "mma.sync.aligned.m16n8k16.row.col.f32.bf16.bf16.f32 "
        "{%0,%1,%2,%3}, {%4,%5,%6,%7}, {%8,%9}, {%0,%1,%2,%3};"
        : "+f"(d[0]), "+f"(d[1]), "+f"(d[2]), "+f"(d[3])
        : "r"(a[0]), "r"(a[1]), "r"(a[2]), "r"(a[3]), "r"(b0), "r"(b1));
}

// ---------------- HMMA NT GEMM with K-concat split, templated tile-M ----------------
// Tile = (MW*64) x 128. 256 threads / 8 warps: MW m-warps x (8/MW) n-warps.
// C[i][j] = sum over segs { A[i][off_a+k] * B[j][off_b+k] }, segs = (0,0),(K,0),(0,K)
// Early refill: stage (c+2)%3 refilled with chunk c+2 BEFORE mma of chunk c (its old
// occupant chunk c-1 was consumed last iter; the single barrier protects it).
template<int MW>
__global__ __launch_bounds__(256) void hm_gemm(
    const bf16* __restrict__ A, const bf16* __restrict__ B, float* __restrict__ C,
    int lda, int ldb, int ldc, size_t aH, size_t bH, size_t cH, int K)
{
    extern __shared__ char dsm[];
    constexpr int MROWS = MW * 64;
    constexpr int NT = 2 * MW;                    // n-tiles (of 8) per warp
    constexpr uint32_t ABYTES = (uint32_t)MROWS * 128u;
    constexpr uint32_t STGB = ABYTES + 16384u;    // A tile + B tile (128x64 bf16)

    A += blockIdx.z * aH;  B += blockIdx.z * bH;  C += blockIdx.z * cH;
    const int i0 = blockIdx.y * MROWS, j0 = blockIdx.x * 128;
    const int tid = threadIdx.x;
    const int nkc = K >> 6;
    const int NC  = 3 * nkc;

    const uint32_t stage0 = (s2u(dsm) + 1023u) & ~1023u;

    const int lane = tid & 31, wid = tid >> 5;
    const int wm = wid % MW, wn = wid / MW;
    const int lt = lane >> 3, lr = lane & 7;
    const int arow = wm * 64 + (lt & 1) * 8 + lr;        // + mt*16
    const int brow = wn * (NT * 8) + (lt & 1) * 8 + lr;  // + np*16
    const int kbsub = (lt >> 1) * 16;
    const uint32_t xm = (uint32_t)(lr << 4);

    float acc[4][NT][4];
#pragma unroll
    for (int i = 0; i < 4; i++)
#pragma unroll
        for (int j = 0; j < NT; j++)
#pragma unroll
            for (int q = 0; q < 4; q++) acc[i][j][q] = 0.0f;

    // issue loads for one stage with chunk c (no commit)
    auto fill = [&](int s, int c) {
        const int seg = c / nkc, kk = (c - seg * nkc) << 6;
        const bf16* Ab = A + ((seg == 1) ? K : 0) + kk;
        const bf16* Bb = B + ((seg == 2) ? K : 0) + kk;
        const uint32_t sA = stage0 + (uint32_t)s * STGB, sB = sA + ABYTES;
#pragma unroll
        for (int i = 0; i < 2 * MW; i++) {
            const int id = (i << 8) + tid;
            const int row = id >> 3, c16 = id & 7;
            const uint32_t so = SWZ((uint32_t)((row << 7) + (c16 << 4)));
            cpasync16(sA + so, Ab + (size_t)(i0 + row) * lda + (c16 << 3));
        }
#pragma unroll
        for (int i = 0; i < 4; i++) {
            const int id = (i << 8) + tid;
            const int row = id >> 3, c16 = id & 7;
            const uint32_t so = SWZ((uint32_t)((row << 7) + (c16 << 4)));
            cpasync16(sB + so, Bb + (size_t)(j0 + row) * ldb + (c16 << 3));
        }
    };

#pragma unroll
    for (int c = 0; c < STAGES; c++) { fill(c, c); CP_COMMIT(); }

    for (int c = 0; c < NC; ++c) {
        const int s = c - (c / STAGES) * STAGES;
        CP_WAIT(1);                 // chunk c resident (one group may remain in flight)
        __syncthreads();            // everyone done with stage (c+2)%3's old chunk
        if (c >= 1) {               // early refill, overlaps with this chunk's MMAs
            const int cn = c + 2;
            if (cn < NC) fill(cn - (cn / STAGES) * STAGES, cn);
            CP_COMMIT();            // always commit to keep group accounting exact
        }
        const uint32_t sA = stage0 + (uint32_t)s * STGB, sB = sA + ABYTES;
#pragma unroll
        for (int ks = 0; ks < 4; ks++) {
            const uint32_t koff = ((uint32_t)(ks * 32 + kbsub)) ^ xm;
            uint32_t a[4][4], b[MW][4];
#pragma unroll
            for (int mt = 0; mt < 4; mt++)
                ldsm4(a[mt][0], a[mt][1], a[mt][2], a[mt][3],
                      sA + (uint32_t)((arow + mt * 16) << 7) + koff);
#pragma unroll
            for (int np = 0; np < MW; np++)
                ldsm4(b[np][0], b[np][1], b[np][2], b[np][3],
                      sB + (uint32_t)((brow + np * 16) << 7) + koff);
#pragma unroll
            for (int mt = 0; mt < 4; mt++)
#pragma unroll
                for (int nt = 0; nt < NT; nt++)
                    mma16816(acc[mt][nt], a[mt], b[nt >> 1][nt & 1], b[nt >> 1][(nt & 1) + 2]);
        }
    }

    // epilogue: direct float2 stores (32B-sector aligned)
    const int rq = lane >> 2, cq = (lane & 3) * 2;
#pragma unroll
    for (int mt = 0; mt < 4; mt++) {
        const int row = i0 + wm * 64 + mt * 16 + rq;
#pragma unroll
        for (int nt = 0; nt < NT; nt++) {
            const int col = j0 + wn * (NT * 8) + nt * 8 + cq;
            *(float2*)(C + (size_t)row * ldc + col)       = make_float2(acc[mt][nt][0], acc[mt][nt][1]);
            *(float2*)(C + (size_t)(row + 8) * ldc + col) = make_float2(acc[mt][nt][2], acc[mt][nt][3]);
        }
    }
}

// ---------------- fp32 -> bf16 hi|lo split (no transpose) ----------------
__global__ __launch_bounds__(256) void split_x(const float* __restrict__ xc, const float* __restrict__ xr)
{
    const size_t i = (size_t)blockIdx.x * 256 + threadIdx.x;  // over 2048*1024
    const int n = (int)(i >> 10), c = (int)(i & 1023);
    const float v = (blockIdx.z == 0 ? xc : xr)[i];
    bf16* o = (blockIdx.z == 0 ? g_Xc : g_Xr) + (size_t)n * 2048 + c;
    const bf16 h = __float2bfloat16(v);
    o[0] = h;  o[1024] = __float2bfloat16(v - __bfloat162float(h));
}

// ---------------- transpose + split: in fp32 [R][C] -> out bf16 [C][ldout], lo at +R ------
__global__ __launch_bounds__(256) void transpose_split(
    const float* __restrict__ in, bf16* __restrict__ out,
    int R, int C, int ldin, int ldout, size_t zin, size_t zout)
{
    __shared__ float t[32][33];
    in  += (size_t)blockIdx.z * zin;
    out += (size_t)blockIdx.z * zout;
    const int r0 = blockIdx.y * 32, c0 = blockIdx.x * 32;
    const int tx = threadIdx.x & 31, ty = threadIdx.x >> 5;
#pragma unroll
    for (int i = 0; i < 4; i++)
        t[ty + i * 8][tx] = in[(size_t)(r0 + ty + i * 8) * ldin + c0 + tx];
    __syncthreads();
#pragma unroll
    for (int i = 0; i < 4; i++) {
        const int cc = ty + i * 8;
        const float v = t[tx][cc];
        const bf16 h = __float2bfloat16(v);
        out[(size_t)(c0 + cc) * ldout + r0 + tx]     = h;
        out[(size_t)(c0 + cc) * ldout + R + r0 + tx] = __float2bfloat16(v - __bfloat162float(h));
    }
}

// ---------------- L2-normalize + split into per-head K-major bf16 hi|lo ----------------
__global__ __launch_bounds__(256) void normalize_k()
{
    const int gid  = blockIdx.x * 8 + (threadIdx.x >> 5);
    const int lane = threadIdx.x & 31;
    const int op  = gid / (NTOK * HEADS);
    const int rem = gid - op * (NTOK * HEADS);
    const int n = rem >> 3, h = rem & 7;

    const float* src; bf16* dst;
    if (op == 0)      { src = g_qkv_cls + (size_t)n * 3072 + h * 128;        dst = g_qc; }
    else if (op == 1) { src = g_qkv_cls + (size_t)n * 3072 + 1024 + h * 128; dst = g_kc; }
    else if (op == 2) { src = g_qk_reg  + (size_t)n * 2048 + h * 128;        dst = g_qr; }
    else if (op == 3) { src = g_qk_reg  + (size_t)n * 2048 + 1024 + h * 128; dst = g_kr; }
    else              { src = g_qkv_cls + (size_t)n * 3072 + 2048 + h * 128; dst = g_vn; }
    dst += ((size_t)h * NTOK + n) * 256;

    float4 v = *(const float4*)(src + lane * 4);
    float ss = v.x * v.x + v.y * v.y + v.z * v.z + v.w * v.w;
#pragma unroll
    for (int o = 16; o; o >>= 1) ss += __shfl_xor_sync(0xffffffffu, ss, o);
    const float r = 1.0f / sqrtf(ss);
    float a[4] = { v.x * r, v.y * r, v.z * r, v.w * r };
#pragma unroll
    for (int j = 0; j < 4; j++) {
        const bf16 h2 = __float2bfloat16(a[j]);
        dst[lane * 4 + j]       = h2;
        dst[128 + lane * 4 + j] = __float2bfloat16(a[j] - __bfloat162float(h2));
    }
}

// ---------------- FMA-only exp + block reductions ----------------
__device__ __forceinline__ float fast_exp(float x)
{
    float t = x * 1.4426950408889634f;
    t = fmaxf(t, -120.0f);
    float r = t + 12582912.0f;
    float f = t - (r - 12582912.0f);
    int   k = __float_as_int(r) - 0x4B400000;
    float p = 1.5403530393381609e-4f;
    p = fmaf(p, f, 1.3333558146428443e-3f);
    p = fmaf(p, f, 9.618129107628477e-3f);
    p = fmaf(p, f, 5.550410866482158e-2f);
    p = fmaf(p, f, 2.402265069591007e-1f);
    p = fmaf(p, f, 6.931471805599453e-1f);
    p = fmaf(p, f, 1.0f);
    return p * __int_as_float((k + 127) << 23);
}
__device__ __forceinline__ float block_max(float v, float* red)
{
#pragma unroll
    for (int o = 16; o; o >>= 1) v = fmaxf(v, __shfl_xor_sync(0xffffffffu, v, o));
    if ((threadIdx.x & 31) == 0) red[threadIdx.x >> 5] = v;
    __syncthreads();
    float r = red[0];
#pragma unroll
    for (int i = 1; i < 8; i++) r = fmaxf(r, red[i]);
    __syncthreads();
    return r;
}
__device__ __forceinline__ float block_sum(float v, float* red)
{
#pragma unroll
    for (int o = 16; o; o >>= 1) v += __shfl_xor_sync(0xffffffffu, v, o);
    if ((threadIdx.x & 31) == 0) red[threadIdx.x >> 5] = v;
    __syncthreads();
    float r = red[0];
#pragma unroll
    for (int i = 1; i < 8; i++) r += red[i];
    __syncthreads();
    return r;
}

// ---------------- fused masked dual softmax + combine + sim_round2 -----------------
// Static softmax shift: |s|<=1 (normalized vectors) => logit <= 25*max(score); a fixed
// upper bound is a valid shift (args in [-50,0], no fp32 underflow) -> no per-head
// row-max reductions needed. Mathematically identical softmax.
__global__ __launch_bounds__(256) void row_fuse(
    const float* __restrict__ cls_score, const float* __restrict__ fg_score,
    float* __restrict__ out_sim)
{
    const int n = blockIdx.x;
    const int tid = threadIdx.x;
    __shared__ float s_sc[NTOK];
    __shared__ float s_fs[NTOK];
    __shared__ float red[8];

    float lsc = -1e30f, lfs = -1e30f;
#pragma unroll
    for (int j = 0; j < 8; j++) {
        const int m = tid + j * 256;
        const float a = cls_score[m], b = fg_score[m];
        s_sc[m] = a;  s_fs[m] = b;
        lsc = fmaxf(lsc, a);  lfs = fmaxf(lfs, b);
    }
    __syncthreads();
    const float Mc = 25.0f * block_max(lsc, red) + 1.0f;   // +1 slack for s slightly > 1
    const float Mr = 25.0f * block_max(lfs, red) + 1.0f;
    const float cthr = s_sc[n] - 0.1f;
    const float fthr = s_fs[n] - 0.1f;

    float simacc[8], vvacc[8];
#pragma unroll
    for (int j = 0; j < 8; j++) { simacc[j] = 0.0f; vvacc[j] = 0.0f; }

    for (int h = 0; h < HEADS; h++) {
        const size_t base = ((size_t)h * NTOK + n) * NTOK;
        bf16* Pb = g_P + ((size_t)h * NTOK + n) * 4096;
        float ec[8], er[8];

        float smc = 0.0f;
#pragma unroll
        for (int j = 0; j < 8; j++) {
            const int m = tid + j * 256;
            const float s  = g_Scls[base + m];
            const float sc = s_sc[m];
            const float l  = (sc > cthr) ? s * (25.0f * sc) : 0.0f;
            ec[j] = fast_exp(l - Mc);  smc += ec[j];
        }
        float smr = 0.0f;
#pragma unroll
        for (int j = 0; j < 8; j++) {
            const int m = tid + j * 256;
            const float s  = g_Sreg[base + m];
            const float sc = s_fs[m];
            const float l  = (sc > fthr) ? s * (25.0f * sc) : 0.0f;
            er[j] = fast_exp(l - Mr);  smr += er[j];
        }
        smc = block_sum(smc, red);
        smr = block_sum(smr, red);
        const float ic = 0.5f / smc, ir = 0.5f / smr;
#pragma unroll
        for (int j = 0; j < 8; j++) {
            const int m = tid + j * 256;
            const float pv = ec[j] * ic + er[j] * ir;
            const bf16 hh = __float2bfloat16(pv);
            Pb[m]        = hh;
            Pb[2048 + m] = __float2bfloat16(pv - __bfloat162float(hh));
            simacc[j] += pv;
            vvacc[j]  += g_Svv[base + m];
        }
    }

    // sim_round2: softmax(mean_h P) [static shift 1: mean-P in (0,1]] masked, renorm
    float sm = 0.0f;
#pragma unroll
    for (int j = 0; j < 8; j++) { simacc[j] = fast_exp(simacc[j] * 0.125f - 1.0f); sm += simacc[j]; }
    sm = block_sum(sm, red);
    float msum = 0.0f;
#pragma unroll
    for (int j = 0; j < 8; j++) {
        const float soft = simacc[j] / sm;
        const float keep = (vvacc[j] * 0.125f > 0.75f) ? soft : 0.0f;
        simacc[j] = keep; msum += keep;
    }
    msum = block_sum(msum, red);
    const float rn = 1.0f / msum;
#pragma unroll
    for (int j = 0; j < 8; j++)
        out_sim[(size_t)n * NTOK + tid + j * 256] = simacc[j] * rn;
}

// ---------------- x_ori copy ----------------
__global__ __launch_bounds__(256) void copy_xori(float* __restrict__ out)
{
    const size_t i = (size_t)blockIdx.x * 256 + threadIdx.x;
    const int n = (int)(i >> 10);
    const int c = (int)(i & 1023);
    out[(size_t)n * 2048 + 1024 + c] = g_qkv_cls[(size_t)n * 3072 + 2048 + c];
}

// -------------------------------- launch ----------------------------------------
extern "C" void kernel_launch(void* const* d_in, const int* in_sizes, int n_in,
                              void* d_out, int out_size)
{
    (void)in_sizes; (void)n_in; (void)out_size;
    const float* x_cls     = (const float*)d_in[0];
    const float* x_reg     = (const float*)d_in[1];
    const float* cls_score = (const float*)d_in[2];
    const float* fg_score  = (const float*)d_in[3];
    const float* W_cls     = (const float*)d_in[4];
    const float* W_reg     = (const float*)d_in[5];
    float* out = (float*)d_out;

    float *qkv_cls, *qk_reg, *Scls, *Sreg, *Svv;
    bf16 *Xc, *Xr, *Wc, *Wr, *qc, *kc, *qr, *kr, *vn, *Vt, *P;
    cudaGetSymbolAddress((void**)&qkv_cls, g_qkv_cls);
    cudaGetSymbolAddress((void**)&qk_reg,  g_qk_reg);
    cudaGetSymbolAddress((void**)&Xc, g_Xc);  cudaGetSymbolAddress((void**)&Xr, g_Xr);
    cudaGetSymbolAddress((void**)&Wc, g_Wc);  cudaGetSymbolAddress((void**)&Wr, g_Wr);
    cudaGetSymbolAddress((void**)&qc, g_qc);  cudaGetSymbolAddress((void**)&kc, g_kc);
    cudaGetSymbolAddress((void**)&qr, g_qr);  cudaGetSymbolAddress((void**)&kr, g_kr);
    cudaGetSymbolAddress((void**)&vn, g_vn);  cudaGetSymbolAddress((void**)&Vt, g_Vt);
    cudaGetSymbolAddress((void**)&Scls, g_Scls);
    cudaGetSymbolAddress((void**)&Sreg, g_Sreg);
    cudaGetSymbolAddress((void**)&Svv,  g_Svv);
    cudaGetSymbolAddress((void**)&P,    g_P);

    const int DS2 = STAGES * 32768 + 1024;   // MW=2: (128+128)x128B stages
    const int DS1 = STAGES * 24576 + 1024;   // MW=1: (64+128)x128B stages
    cudaFuncSetAttribute(hm_gemm<2>, cudaFuncAttributeMaxDynamicSharedMemorySize, DS2);
    cudaFuncSetAttribute(hm_gemm<1>, cudaFuncAttributeMaxDynamicSharedMemorySize, DS1);

    const size_t SH = (size_t)NTOK * NTOK;
    const size_t QH = (size_t)NTOK * 256;

    // 1) split inputs, transpose+split weights
    split_x<<<dim3(8192, 1, 2), 256>>>(x_cls, x_reg);
    transpose_split<<<dim3(96, 32, 1), 256>>>(W_cls, Wc, 1024, 3072, 3072, 2048, 0, 0);
    transpose_split<<<dim3(64, 32, 1), 256>>>(W_reg, Wr, 1024, 2048, 3072, 2048, 0, 0);

    // 2) qkv projections (HMMA, split fp32 emulation)
    hm_gemm<2><<<dim3(24, 16, 1), 256, DS2>>>(Xc, Wc, qkv_cls, 2048, 2048, 3072, 0, 0, 0, 1024);
    hm_gemm<2><<<dim3(16, 16, 1), 256, DS2>>>(Xr, Wr, qk_reg,  2048, 2048, 2048, 0, 0, 0, 1024);

    // 3) normalize q/k/v -> per-head split bf16; transpose v -> Vt split
    normalize_k<<<5 * NTOK * HEADS / 8, 256>>>();
    transpose_split<<<dim3(4, 64, 8), 256>>>(qkv_cls + 2048, Vt, 2048, 128, 3072, 4096,
                                             128, (size_t)128 * 4096);

    // 4) score GEMMs (batched over heads)
    hm_gemm<2><<<dim3(16, 16, 8), 256, DS2>>>(qc, kc, Scls, 256, 256, 2048, QH, QH, SH, 128);
    hm_gemm<2><<<dim3(16, 16, 8), 256, DS2>>>(qr, kr, Sreg, 256, 256, 2048, QH, QH, SH, 128);
    hm_gemm<2><<<dim3(16, 16, 8), 256, DS2>>>(vn, vn, Svv,  256, 256, 2048, QH, QH, SH, 128);

    // 5) fused softmax etc; writes P (bf16 hi|lo) + sim output
    row_fuse<<<NTOK, 256>>>(cls_score, fg_score, out + (size_t)NTOK * NTOK);

    // 6) x = P @ V  -> out[:, 0:1024] per head (64-row tiles -> 256 CTAs)
    hm_gemm<1><<<dim3(1, 32, 8), 256, DS1>>>(P, Vt, out, 4096, 4096, 2048,
                                             (size_t)NTOK * 4096, (size_t)128 * 4096, 128, 2048);

    // 7) x_ori copy -> out[:, 1024:2048]
    copy_xori<<<(NTOK * 1024) / 256, 256>>>(out);
}